// round 2
// baseline (speedup 1.0000x reference)
#include <cuda_runtime.h>
#include <cuda_bf16.h>
#include <cstdint>

#define EMB 64
#define HID 256
#define SEQ 200
#define BATCH 4096

// -------- device scratch (no allocations allowed) --------
__device__ __align__(16) __nv_bfloat16 g_Wt[256 * 128];   // folded attn W, [n][k] layout
__device__ __align__(16) float        g_Mt[64 * 256];     // W1[64:128]-W1[128:192], [e][n]
__device__ __align__(16) float        g_x[BATCH * 128];   // [interest | t] per batch row

// ================= kernel 0: fold attention weights =================
__global__ void prep_kernel(const float* __restrict__ aw1) {
    int idx = blockIdx.x * 256 + threadIdx.x;      // 0..32767
    int n = idx >> 7, k = idx & 127;
    // rows 0..63 of folded W = W1[0:64]+W1[128:192]; rows 64..127 = W1[192:256]
    float v = aw1[(128 + k) * HID + n];
    if (k < 64) v += aw1[k * HID + n];
    g_Wt[n * 128 + k] = __float2bfloat16(v);
    if (idx < 64 * 256) {
        int e = idx >> 8, nn = idx & 255;
        g_Mt[idx] = aw1[(64 + e) * HID + nn] - aw1[(128 + e) * HID + nn];
    }
}

// ================= kernel 1: gather + attention GEMM + softmax + pool =================
struct Smem1 {
    __nv_bfloat16 A[208 * 136];   // [h | h*t] bf16, padded stride 136
    __nv_bfloat16 W[256 * 136];   // folded W, [n][k], padded stride 136
    float h[200 * 64];            // fp32 history embeddings (for pooling)
    float t[64];
    float cb[256];                // per-batch bias
    float w2[256];                // attn_w2
    float logits[208];
    float part[256];
    float red[40];
};

__device__ __forceinline__ void mma16816(float& c0, float& c1, float& c2, float& c3,
                                         uint32_t a0, uint32_t a1, uint32_t a2, uint32_t a3,
                                         uint32_t b0, uint32_t b1) {
    asm volatile(
        "mma.sync.aligned.m16n8k16.row.col.f32.bf16.bf16.f32 "
        "{%0,%1,%2,%3}, {%4,%5,%6,%7}, {%8,%9}, {%0,%1,%2,%3};\n"
        : "+f"(c0), "+f"(c1), "+f"(c2), "+f"(c3)
        : "r"(a0), "r"(a1), "r"(a2), "r"(a3), "r"(b0), "r"(b1));
}

__global__ __launch_bounds__(256, 1) void din_main(
    const int* __restrict__ uh, const int* __restrict__ ti,
    const float* __restrict__ uemb, const float* __restrict__ iemb,
    const float* __restrict__ ab1, const float* __restrict__ aw2)
{
    extern __shared__ char smraw[];
    Smem1& sm = *reinterpret_cast<Smem1*>(smraw);
    const int tid = threadIdx.x;
    const int b = blockIdx.x;

    if (tid < 64) sm.t[tid] = iemb[(long)ti[b] * EMB + tid];
    __syncthreads();

    uint32_t* Au = reinterpret_cast<uint32_t*>(sm.A);
    uint32_t* Wu = reinterpret_cast<uint32_t*>(sm.W);

    // ---- gather h, build A = [h | h*t] bf16 ----
    {
        const float4* ue4 = reinterpret_cast<const float4*>(uemb);
        const int* hist = uh + b * SEQ;
        for (int i = tid; i < SEQ * 16; i += 256) {
            int row = i >> 4, q = i & 15;
            float4 v = ue4[(long)hist[row] * 16 + q];
            *reinterpret_cast<float4*>(sm.h + row * EMB + q * 4) = v;
            float t0 = sm.t[q * 4 + 0], t1 = sm.t[q * 4 + 1];
            float t2 = sm.t[q * 4 + 2], t3 = sm.t[q * 4 + 3];
            __nv_bfloat162 p0 = __floats2bfloat162_rn(v.x, v.y);
            __nv_bfloat162 p1 = __floats2bfloat162_rn(v.z, v.w);
            __nv_bfloat162 q0 = __floats2bfloat162_rn(v.x * t0, v.y * t1);
            __nv_bfloat162 q1 = __floats2bfloat162_rn(v.z * t2, v.w * t3);
            int base = row * 68 + q * 2;
            Au[base]      = *reinterpret_cast<uint32_t*>(&p0);
            Au[base + 1]  = *reinterpret_cast<uint32_t*>(&p1);
            Au[base + 32] = *reinterpret_cast<uint32_t*>(&q0);
            Au[base + 33] = *reinterpret_cast<uint32_t*>(&q1);
        }
        // zero-pad rows 200..207
        for (int i = tid; i < 8 * 68; i += 256) Au[200 * 68 + i] = 0u;
    }

    // ---- copy folded W ----
    {
        const uint32_t* Wg = reinterpret_cast<const uint32_t*>(g_Wt);
        for (int i = tid; i < 256 * 64; i += 256) {
            int n = i >> 6, j = i & 63;
            Wu[n * 68 + j] = Wg[i];
        }
    }

    // ---- per-batch bias c_b = b1 + t @ Mt, and w2 ----
    {
        float acc = ab1[tid];
        #pragma unroll 8
        for (int e = 0; e < 64; e++) acc = fmaf(sm.t[e], g_Mt[e * 256 + tid], acc);
        sm.cb[tid] = acc;
        sm.w2[tid] = aw2[tid];
    }
    __syncthreads();

    // ---- GEMM + fused logit epilogue ----
    const int warp = tid >> 5, lane = tid & 31;
    const int lr = lane >> 2, lc = lane & 3;
    for (int slab = warp; slab < 13; slab += 8) {
        uint32_t a[8][4];
        int r0 = slab * 16 + lr;
        #pragma unroll
        for (int ks = 0; ks < 8; ks++) {
            a[ks][0] = Au[r0 * 68 + ks * 8 + lc];
            a[ks][1] = Au[(r0 + 8) * 68 + ks * 8 + lc];
            a[ks][2] = Au[r0 * 68 + ks * 8 + lc + 4];
            a[ks][3] = Au[(r0 + 8) * 68 + ks * 8 + lc + 4];
        }
        float lp0 = 0.f, lp1 = 0.f;
        for (int nt = 0; nt < 32; nt++) {
            int nb = nt * 8 + lr;
            float c0 = 0.f, c1 = 0.f, c2 = 0.f, c3 = 0.f;
            #pragma unroll
            for (int ks = 0; ks < 8; ks++) {
                uint32_t b0 = Wu[nb * 68 + ks * 8 + lc];
                uint32_t b1 = Wu[nb * 68 + ks * 8 + lc + 4];
                mma16816(c0, c1, c2, c3, a[ks][0], a[ks][1], a[ks][2], a[ks][3], b0, b1);
            }
            int n0 = nt * 8 + lc * 2, n1 = n0 + 1;
            float cb0 = sm.cb[n0], cb1 = sm.cb[n1];
            float w20 = sm.w2[n0], w21 = sm.w2[n1];
            lp0 += fmaxf(c0 + cb0, 0.f) * w20 + fmaxf(c1 + cb1, 0.f) * w21;
            lp1 += fmaxf(c2 + cb0, 0.f) * w20 + fmaxf(c3 + cb1, 0.f) * w21;
        }
        lp0 += __shfl_xor_sync(0xffffffffu, lp0, 1);
        lp0 += __shfl_xor_sync(0xffffffffu, lp0, 2);
        lp1 += __shfl_xor_sync(0xffffffffu, lp1, 1);
        lp1 += __shfl_xor_sync(0xffffffffu, lp1, 2);
        if (lc == 0) {
            sm.logits[slab * 16 + lr] = lp0;
            sm.logits[slab * 16 + lr + 8] = lp1;
        }
    }
    __syncthreads();

    // ---- softmax over 200 logits ----
    {
        float v = (tid < SEQ) ? sm.logits[tid] : -1e30f;
        float m = v;
        #pragma unroll
        for (int o = 16; o > 0; o >>= 1) m = fmaxf(m, __shfl_xor_sync(0xffffffffu, m, o));
        if (lane == 0) sm.red[warp] = m;
        __syncthreads();
        if (tid == 0) {
            float mm = sm.red[0];
            #pragma unroll
            for (int w = 1; w < 8; w++) mm = fmaxf(mm, sm.red[w]);
            sm.red[8] = mm;
        }
        __syncthreads();
        float mm = sm.red[8];
        float ev = (tid < SEQ) ? __expf(v - mm) : 0.f;
        float s = ev;
        #pragma unroll
        for (int o = 16; o > 0; o >>= 1) s += __shfl_xor_sync(0xffffffffu, s, o);
        if (lane == 0) sm.red[16 + warp] = s;
        __syncthreads();
        if (tid == 0) {
            float ss = 0.f;
            #pragma unroll
            for (int w = 0; w < 8; w++) ss += sm.red[16 + w];
            sm.red[9] = 1.f / ss;
        }
        __syncthreads();
        if (tid < SEQ) sm.logits[tid] = ev * sm.red[9];
    }
    __syncthreads();

    // ---- weighted pooling: interest[e] = sum_s att[s] * h[s][e] ----
    {
        int e = tid & 63, chunk = tid >> 6;
        float acc = 0.f;
        #pragma unroll 5
        for (int s = chunk * 50; s < chunk * 50 + 50; s++)
            acc = fmaf(sm.logits[s], sm.h[s * EMB + e], acc);
        sm.part[tid] = acc;
    }
    __syncthreads();
    if (tid < 64) {
        float v = sm.part[tid] + sm.part[64 + tid] + sm.part[128 + tid] + sm.part[192 + tid];
        g_x[b * 128 + tid] = v;
        g_x[b * 128 + 64 + tid] = sm.t[tid];
    }
}

// ================= kernel 2: prediction head =================
struct Smem2 {
    float w1[128 * 256];
    float b1[256];
    float w2[256];
    float xs[8 * 4 * 128];   // 8 warps x 4 rows x 128
};

__global__ __launch_bounds__(256, 1) void din_mlp(
    const float* __restrict__ mw1, const float* __restrict__ mb1,
    const float* __restrict__ mw2, const float* __restrict__ mb2,
    float* __restrict__ out)
{
    extern __shared__ char smraw[];
    Smem2& sm = *reinterpret_cast<Smem2*>(smraw);
    const int tid = threadIdx.x;

    for (int i = tid; i < 128 * 256; i += 256) sm.w1[i] = mw1[i];
    sm.b1[tid] = mb1[tid];
    sm.w2[tid] = mw2[tid];
    __syncthreads();

    const int warp = tid >> 5, lane = tid & 31;
    const int row0 = blockIdx.x * 32 + warp * 4;

    float4* xs4 = reinterpret_cast<float4*>(sm.xs + warp * 512);
    const float4* gx4 = reinterpret_cast<const float4*>(g_x);
    #pragma unroll
    for (int r = 0; r < 4; r++) xs4[r * 32 + lane] = gx4[(long)(row0 + r) * 32 + lane];
    __syncwarp();

    float d[4][8];
    #pragma unroll
    for (int r = 0; r < 4; r++)
        #pragma unroll
        for (int u = 0; u < 8; u++) d[r][u] = sm.b1[u * 32 + lane];

    const float* xw = sm.xs + warp * 512;
    for (int k = 0; k < 128; k++) {
        float w[8];
        #pragma unroll
        for (int u = 0; u < 8; u++) w[u] = sm.w1[k * 256 + u * 32 + lane];
        #pragma unroll
        for (int r = 0; r < 4; r++) {
            float xk = xw[r * 128 + k];
            #pragma unroll
            for (int u = 0; u < 8; u++) d[r][u] = fmaf(xk, w[u], d[r][u]);
        }
    }

    float b2v = mb2[0];
    float acc[4];
    #pragma unroll
    for (int r = 0; r < 4; r++) {
        float a = 0.f;
        #pragma unroll
        for (int u = 0; u < 8; u++) a += fmaxf(d[r][u], 0.f) * sm.w2[u * 32 + lane];
        #pragma unroll
        for (int o = 16; o > 0; o >>= 1) a += __shfl_xor_sync(0xffffffffu, a, o);
        acc[r] = a;
    }
    if (lane < 4) {
        float z = acc[lane] + b2v;
        out[row0 + lane] = 1.f / (1.f + __expf(-z));
    }
}

// ================= launch =================
extern "C" void kernel_launch(void* const* d_in, const int* in_sizes, int n_in,
                              void* d_out, int out_size) {
    const int*   uh   = (const int*)d_in[0];
    const int*   ti   = (const int*)d_in[1];
    const float* uemb = (const float*)d_in[2];
    const float* iemb = (const float*)d_in[3];
    const float* aw1  = (const float*)d_in[4];
    const float* ab1  = (const float*)d_in[5];
    const float* aw2  = (const float*)d_in[6];
    // d_in[7] attn_b2: softmax-invariant, unused
    const float* mw1  = (const float*)d_in[8];
    const float* mb1  = (const float*)d_in[9];
    const float* mw2  = (const float*)d_in[10];
    const float* mb2  = (const float*)d_in[11];
    float* out = (float*)d_out;

    cudaFuncSetAttribute(din_main, cudaFuncAttributeMaxDynamicSharedMemorySize, (int)sizeof(Smem1));
    cudaFuncSetAttribute(din_mlp,  cudaFuncAttributeMaxDynamicSharedMemorySize, (int)sizeof(Smem2));

    prep_kernel<<<128, 256>>>(aw1);
    din_main<<<BATCH, 256, sizeof(Smem1)>>>(uh, ti, uemb, iemb, ab1, aw2);
    din_mlp<<<128, 256, sizeof(Smem2)>>>(mw1, mb1, mw2, mb2, out);
}

// round 3
// speedup vs baseline: 1.0003x; 1.0003x over previous
#include <cuda_runtime.h>
#include <cuda_bf16.h>
#include <cstdint>

#define EMB 64
#define HID 256
#define SEQ 200
#define BATCH 4096

// -------- device scratch (no allocations allowed) --------
__device__ __align__(16) __nv_bfloat16 g_Wt[256 * 128];   // folded attn W, [n][k] layout
__device__ __align__(16) float        g_Mt[64 * 256];     // W1[64:128]-W1[128:192], [e][n]
__device__ __align__(16) float        g_x[BATCH * 128];   // [interest | t] per batch row

// ================= kernel 0: fold attention weights =================
__global__ void prep_kernel(const float* __restrict__ aw1) {
    int idx = blockIdx.x * 256 + threadIdx.x;      // 0..32767
    int n = idx >> 7, k = idx & 127;
    // rows 0..63 of folded W = W1[0:64]+W1[128:192]; rows 64..127 = W1[192:256]
    float v = aw1[(128 + k) * HID + n];
    if (k < 64) v += aw1[k * HID + n];
    g_Wt[n * 128 + k] = __float2bfloat16(v);
    if (idx < 64 * 256) {
        int e = idx >> 8, nn = idx & 255;
        g_Mt[idx] = aw1[(64 + e) * HID + nn] - aw1[(128 + e) * HID + nn];
    }
}

// ================= kernel 1: gather + attention GEMM + softmax + pool =================
struct Smem1 {
    __nv_bfloat16 A[208 * 136];   // [h | h*t] bf16, padded stride 136
    __nv_bfloat16 W[256 * 136];   // folded W, [n][k], padded stride 136
    float h[200 * 64];            // fp32 history embeddings (for pooling)
    float t[64];
    float cb[256];                // per-batch bias
    float w2[256];                // attn_w2
    float logits[208];
    float part[256];
    float red[40];
};

__device__ __forceinline__ void mma16816(float& c0, float& c1, float& c2, float& c3,
                                         uint32_t a0, uint32_t a1, uint32_t a2, uint32_t a3,
                                         uint32_t b0, uint32_t b1) {
    asm volatile(
        "mma.sync.aligned.m16n8k16.row.col.f32.bf16.bf16.f32 "
        "{%0,%1,%2,%3}, {%4,%5,%6,%7}, {%8,%9}, {%0,%1,%2,%3};\n"
        : "+f"(c0), "+f"(c1), "+f"(c2), "+f"(c3)
        : "r"(a0), "r"(a1), "r"(a2), "r"(a3), "r"(b0), "r"(b1));
}

__global__ __launch_bounds__(256, 1) void din_main(
    const int* __restrict__ uh, const int* __restrict__ ti,
    const float* __restrict__ uemb, const float* __restrict__ iemb,
    const float* __restrict__ ab1, const float* __restrict__ aw2)
{
    extern __shared__ char smraw[];
    Smem1& sm = *reinterpret_cast<Smem1*>(smraw);
    const int tid = threadIdx.x;
    const int b = blockIdx.x;

    if (tid < 64) sm.t[tid] = iemb[(long)ti[b] * EMB + tid];
    __syncthreads();

    uint32_t* Au = reinterpret_cast<uint32_t*>(sm.A);
    uint32_t* Wu = reinterpret_cast<uint32_t*>(sm.W);

    // ---- gather h, build A = [h | h*t] bf16 ----
    {
        const float4* ue4 = reinterpret_cast<const float4*>(uemb);
        const int* hist = uh + b * SEQ;
        for (int i = tid; i < SEQ * 16; i += 256) {
            int row = i >> 4, q = i & 15;
            float4 v = ue4[(long)hist[row] * 16 + q];
            *reinterpret_cast<float4*>(sm.h + row * EMB + q * 4) = v;
            float t0 = sm.t[q * 4 + 0], t1 = sm.t[q * 4 + 1];
            float t2 = sm.t[q * 4 + 2], t3 = sm.t[q * 4 + 3];
            __nv_bfloat162 p0 = __floats2bfloat162_rn(v.x, v.y);
            __nv_bfloat162 p1 = __floats2bfloat162_rn(v.z, v.w);
            __nv_bfloat162 q0 = __floats2bfloat162_rn(v.x * t0, v.y * t1);
            __nv_bfloat162 q1 = __floats2bfloat162_rn(v.z * t2, v.w * t3);
            int base = row * 68 + q * 2;
            Au[base]      = *reinterpret_cast<uint32_t*>(&p0);
            Au[base + 1]  = *reinterpret_cast<uint32_t*>(&p1);
            Au[base + 32] = *reinterpret_cast<uint32_t*>(&q0);
            Au[base + 33] = *reinterpret_cast<uint32_t*>(&q1);
        }
        // zero-pad rows 200..207
        for (int i = tid; i < 8 * 68; i += 256) Au[200 * 68 + i] = 0u;
    }

    // ---- copy folded W ----
    {
        const uint32_t* Wg = reinterpret_cast<const uint32_t*>(g_Wt);
        for (int i = tid; i < 256 * 64; i += 256) {
            int n = i >> 6, j = i & 63;
            Wu[n * 68 + j] = Wg[i];
        }
    }

    // ---- per-batch bias c_b = b1 + t @ Mt, and w2 ----
    {
        float acc = ab1[tid];
        #pragma unroll 8
        for (int e = 0; e < 64; e++) acc = fmaf(sm.t[e], g_Mt[e * 256 + tid], acc);
        sm.cb[tid] = acc;
        sm.w2[tid] = aw2[tid];
    }
    __syncthreads();

    // ---- GEMM + fused logit epilogue ----
    const int warp = tid >> 5, lane = tid & 31;
    const int lr = lane >> 2, lc = lane & 3;
    for (int slab = warp; slab < 13; slab += 8) {
        uint32_t a[8][4];
        int r0 = slab * 16 + lr;
        #pragma unroll
        for (int ks = 0; ks < 8; ks++) {
            a[ks][0] = Au[r0 * 68 + ks * 8 + lc];
            a[ks][1] = Au[(r0 + 8) * 68 + ks * 8 + lc];
            a[ks][2] = Au[r0 * 68 + ks * 8 + lc + 4];
            a[ks][3] = Au[(r0 + 8) * 68 + ks * 8 + lc + 4];
        }
        float lp0 = 0.f, lp1 = 0.f;
        for (int nt = 0; nt < 32; nt++) {
            int nb = nt * 8 + lr;
            float c0 = 0.f, c1 = 0.f, c2 = 0.f, c3 = 0.f;
            #pragma unroll
            for (int ks = 0; ks < 8; ks++) {
                uint32_t b0 = Wu[nb * 68 + ks * 8 + lc];
                uint32_t b1 = Wu[nb * 68 + ks * 8 + lc + 4];
                mma16816(c0, c1, c2, c3, a[ks][0], a[ks][1], a[ks][2], a[ks][3], b0, b1);
            }
            int n0 = nt * 8 + lc * 2, n1 = n0 + 1;
            float cb0 = sm.cb[n0], cb1 = sm.cb[n1];
            float w20 = sm.w2[n0], w21 = sm.w2[n1];
            lp0 += fmaxf(c0 + cb0, 0.f) * w20 + fmaxf(c1 + cb1, 0.f) * w21;
            lp1 += fmaxf(c2 + cb0, 0.f) * w20 + fmaxf(c3 + cb1, 0.f) * w21;
        }
        lp0 += __shfl_xor_sync(0xffffffffu, lp0, 1);
        lp0 += __shfl_xor_sync(0xffffffffu, lp0, 2);
        lp1 += __shfl_xor_sync(0xffffffffu, lp1, 1);
        lp1 += __shfl_xor_sync(0xffffffffu, lp1, 2);
        if (lc == 0) {
            sm.logits[slab * 16 + lr] = lp0;
            sm.logits[slab * 16 + lr + 8] = lp1;
        }
    }
    __syncthreads();

    // ---- softmax over 200 logits ----
    {
        float v = (tid < SEQ) ? sm.logits[tid] : -1e30f;
        float m = v;
        #pragma unroll
        for (int o = 16; o > 0; o >>= 1) m = fmaxf(m, __shfl_xor_sync(0xffffffffu, m, o));
        if (lane == 0) sm.red[warp] = m;
        __syncthreads();
        if (tid == 0) {
            float mm = sm.red[0];
            #pragma unroll
            for (int w = 1; w < 8; w++) mm = fmaxf(mm, sm.red[w]);
            sm.red[8] = mm;
        }
        __syncthreads();
        float mm = sm.red[8];
        float ev = (tid < SEQ) ? __expf(v - mm) : 0.f;
        float s = ev;
        #pragma unroll
        for (int o = 16; o > 0; o >>= 1) s += __shfl_xor_sync(0xffffffffu, s, o);
        if (lane == 0) sm.red[16 + warp] = s;
        __syncthreads();
        if (tid == 0) {
            float ss = 0.f;
            #pragma unroll
            for (int w = 0; w < 8; w++) ss += sm.red[16 + w];
            sm.red[9] = 1.f / ss;
        }
        __syncthreads();
        if (tid < SEQ) sm.logits[tid] = ev * sm.red[9];
    }
    __syncthreads();

    // ---- weighted pooling: interest[e] = sum_s att[s] * h[s][e] ----
    {
        int e = tid & 63, chunk = tid >> 6;
        float acc = 0.f;
        #pragma unroll 5
        for (int s = chunk * 50; s < chunk * 50 + 50; s++)
            acc = fmaf(sm.logits[s], sm.h[s * EMB + e], acc);
        sm.part[tid] = acc;
    }
    __syncthreads();
    if (tid < 64) {
        float v = sm.part[tid] + sm.part[64 + tid] + sm.part[128 + tid] + sm.part[192 + tid];
        g_x[b * 128 + tid] = v;
        g_x[b * 128 + 64 + tid] = sm.t[tid];
    }
}

// ================= kernel 2: prediction head =================
struct Smem2 {
    float w1[128 * 256];
    float b1[256];
    float w2[256];
    float xs[8 * 4 * 128];   // 8 warps x 4 rows x 128
};

__global__ __launch_bounds__(256, 1) void din_mlp(
    const float* __restrict__ mw1, const float* __restrict__ mb1,
    const float* __restrict__ mw2, const float* __restrict__ mb2,
    float* __restrict__ out)
{
    extern __shared__ char smraw[];
    Smem2& sm = *reinterpret_cast<Smem2*>(smraw);
    const int tid = threadIdx.x;

    for (int i = tid; i < 128 * 256; i += 256) sm.w1[i] = mw1[i];
    sm.b1[tid] = mb1[tid];
    sm.w2[tid] = mw2[tid];
    __syncthreads();

    const int warp = tid >> 5, lane = tid & 31;
    const int row0 = blockIdx.x * 32 + warp * 4;

    float4* xs4 = reinterpret_cast<float4*>(sm.xs + warp * 512);
    const float4* gx4 = reinterpret_cast<const float4*>(g_x);
    #pragma unroll
    for (int r = 0; r < 4; r++) xs4[r * 32 + lane] = gx4[(long)(row0 + r) * 32 + lane];
    __syncwarp();

    float d[4][8];
    #pragma unroll
    for (int r = 0; r < 4; r++)
        #pragma unroll
        for (int u = 0; u < 8; u++) d[r][u] = sm.b1[u * 32 + lane];

    const float* xw = sm.xs + warp * 512;
    for (int k = 0; k < 128; k++) {
        float w[8];
        #pragma unroll
        for (int u = 0; u < 8; u++) w[u] = sm.w1[k * 256 + u * 32 + lane];
        #pragma unroll
        for (int r = 0; r < 4; r++) {
            float xk = xw[r * 128 + k];
            #pragma unroll
            for (int u = 0; u < 8; u++) d[r][u] = fmaf(xk, w[u], d[r][u]);
        }
    }

    float b2v = mb2[0];
    float acc[4];
    #pragma unroll
    for (int r = 0; r < 4; r++) {
        float a = 0.f;
        #pragma unroll
        for (int u = 0; u < 8; u++) a += fmaxf(d[r][u], 0.f) * sm.w2[u * 32 + lane];
        #pragma unroll
        for (int o = 16; o > 0; o >>= 1) a += __shfl_xor_sync(0xffffffffu, a, o);
        acc[r] = a;
    }
    if (lane < 4) {
        float z = acc[lane] + b2v;
        out[row0 + lane] = 1.f / (1.f + __expf(-z));
    }
}

// ================= launch =================
extern "C" void kernel_launch(void* const* d_in, const int* in_sizes, int n_in,
                              void* d_out, int out_size) {
    const int*   uh   = (const int*)d_in[0];
    const int*   ti   = (const int*)d_in[1];
    const float* uemb = (const float*)d_in[2];
    const float* iemb = (const float*)d_in[3];
    const float* aw1  = (const float*)d_in[4];
    const float* ab1  = (const float*)d_in[5];
    const float* aw2  = (const float*)d_in[6];
    // d_in[7] attn_b2: softmax-invariant, unused
    const float* mw1  = (const float*)d_in[8];
    const float* mb1  = (const float*)d_in[9];
    const float* mw2  = (const float*)d_in[10];
    const float* mb2  = (const float*)d_in[11];
    float* out = (float*)d_out;

    cudaFuncSetAttribute(din_main, cudaFuncAttributeMaxDynamicSharedMemorySize, (int)sizeof(Smem1));
    cudaFuncSetAttribute(din_mlp,  cudaFuncAttributeMaxDynamicSharedMemorySize, (int)sizeof(Smem2));

    prep_kernel<<<128, 256>>>(aw1);
    din_main<<<BATCH, 256, sizeof(Smem1)>>>(uh, ti, uemb, iemb, ab1, aw2);
    din_mlp<<<128, 256, sizeof(Smem2)>>>(mw1, mb1, mw2, mb2, out);
}

// round 4
// speedup vs baseline: 1.7313x; 1.7308x over previous
#include <cuda_runtime.h>
#include <cuda_bf16.h>
#include <cstdint>

#define EMB 64
#define HID 256
#define SEQ 200
#define BATCH 4096

// -------- device scratch (no allocations allowed) --------
__device__ __align__(16) __nv_bfloat16 g_Wt[256 * 128];    // folded attn W, [n][k]
__device__ __align__(16) float        g_cb[BATCH * 256];   // per-batch folded bias
__device__ __align__(16) float        g_x[BATCH * 128];    // [interest | t] per batch row

// ================= prep: fold W, gather t, compute c_b =================
struct SmemP {
    float Mt[64 * 256];
    float b1s[256];
    float ts[64];
    int   tis[32];
};

__global__ __launch_bounds__(256) void prep_kernel(
    const float* __restrict__ aw1, const float* __restrict__ ab1,
    const int* __restrict__ ti, const float* __restrict__ iemb)
{
    extern __shared__ char smraw[];
    SmemP& sm = *reinterpret_cast<SmemP*>(smraw);
    const int tid = threadIdx.x;

    // fold Wt slice (128 blocks x 256 threads covers 32768 elements)
    {
        int idx = blockIdx.x * 256 + tid;
        int n = idx >> 7, k = idx & 127;
        float v = aw1[(128 + k) * HID + n];
        if (k < 64) v += aw1[k * HID + n];
        g_Wt[n * 128 + k] = __float2bfloat16(v);
    }
    // Mt[e][n] = W1[64+e][n] - W1[128+e][n]
    for (int i = tid; i < 64 * 256; i += 256) {
        int e = i >> 8, n = i & 255;
        sm.Mt[i] = aw1[(64 + e) * HID + n] - aw1[(128 + e) * HID + n];
    }
    sm.b1s[tid] = ab1[tid];
    if (tid < 32) sm.tis[tid] = ti[blockIdx.x * 32 + tid];
    __syncthreads();

    for (int bb = 0; bb < 32; bb++) {
        if (tid < 64) sm.ts[tid] = iemb[(long)sm.tis[bb] * EMB + tid];
        __syncthreads();
        float acc = sm.b1s[tid];
        #pragma unroll 16
        for (int e = 0; e < 64; e++) acc = fmaf(sm.ts[e], sm.Mt[e * 256 + tid], acc);
        int b = blockIdx.x * 32 + bb;
        g_cb[b * 256 + tid] = acc;
        if (tid < 64) g_x[b * 128 + 64 + tid] = sm.ts[tid];
        __syncthreads();
    }
}

// ================= kernel 1: gather + attention GEMM + softmax + pool =================
struct Smem1 {
    __nv_bfloat16 A[208 * 136];   // [h | h*t] bf16, padded stride 136
    float t[64];
    float cb[256];
    float w2[256];
    float logits[208];
    float red[40];
    int   idx[200];
    float part[8][64];
};

__device__ __forceinline__ void mma16816(float& c0, float& c1, float& c2, float& c3,
                                         uint32_t a0, uint32_t a1, uint32_t a2, uint32_t a3,
                                         uint32_t b0, uint32_t b1) {
    asm volatile(
        "mma.sync.aligned.m16n8k16.row.col.f32.bf16.bf16.f32 "
        "{%0,%1,%2,%3}, {%4,%5,%6,%7}, {%8,%9}, {%0,%1,%2,%3};\n"
        : "+f"(c0), "+f"(c1), "+f"(c2), "+f"(c3)
        : "r"(a0), "r"(a1), "r"(a2), "r"(a3), "r"(b0), "r"(b1));
}

__global__ __launch_bounds__(256, 2) void din_main(
    const int* __restrict__ uh,
    const float* __restrict__ uemb,
    const float* __restrict__ aw2)
{
    extern __shared__ char smraw[];
    Smem1& sm = *reinterpret_cast<Smem1*>(smraw);
    const int tid = threadIdx.x;
    const int b = blockIdx.x;
    uint32_t* Au = reinterpret_cast<uint32_t*>(sm.A);
    const int warp = tid >> 5, lane = tid & 31;
    const int lr = lane >> 2, lc = lane & 3;

    // ---- stage indices, t, cb, w2; zero pads ----
    if (tid < 200) sm.idx[tid] = uh[b * SEQ + tid];
    if (tid >= 192) sm.t[tid - 192] = g_x[b * 128 + 64 + (tid - 192)];
    sm.cb[tid] = g_cb[b * 256 + tid];
    sm.w2[tid] = aw2[tid];
    if (tid < 208) sm.logits[tid] = 0.f;
    for (int i = tid; i < 8 * 68; i += 256) Au[200 * 68 + i] = 0u;  // pad rows 200..207
    __syncthreads();

    // ---- gather h, build A = [h | h*t] bf16 (13 independent loads/thread) ----
    {
        const float4* ue4 = reinterpret_cast<const float4*>(uemb);
        #pragma unroll
        for (int it = 0; it < 13; it++) {
            int i = tid + it * 256;
            if (i < 3200) {
                int row = i >> 4, q = i & 15;
                float4 v = ue4[(long)sm.idx[row] * 16 + q];
                float t0 = sm.t[q * 4 + 0], t1 = sm.t[q * 4 + 1];
                float t2 = sm.t[q * 4 + 2], t3 = sm.t[q * 4 + 3];
                __nv_bfloat162 p0 = __floats2bfloat162_rn(v.x, v.y);
                __nv_bfloat162 p1 = __floats2bfloat162_rn(v.z, v.w);
                __nv_bfloat162 q0 = __floats2bfloat162_rn(v.x * t0, v.y * t1);
                __nv_bfloat162 q1 = __floats2bfloat162_rn(v.z * t2, v.w * t3);
                int base = row * 68 + q * 2;
                uint2 P; P.x = *reinterpret_cast<uint32_t*>(&p0); P.y = *reinterpret_cast<uint32_t*>(&p1);
                uint2 Q; Q.x = *reinterpret_cast<uint32_t*>(&q0); Q.y = *reinterpret_cast<uint32_t*>(&q1);
                *reinterpret_cast<uint2*>(Au + base) = P;
                *reinterpret_cast<uint2*>(Au + base + 32) = Q;
            }
        }
    }

    // ---- B fragments: this warp's 4 n-tiles, straight from L2 into regs ----
    uint32_t Breg[4][8][2];
    {
        const uint32_t* Wg = reinterpret_cast<const uint32_t*>(g_Wt);
        #pragma unroll
        for (int nt = 0; nt < 4; nt++) {
            int nb = (warp * 4 + nt) * 8 + lr;
            #pragma unroll
            for (int ks = 0; ks < 8; ks++) {
                Breg[nt][ks][0] = Wg[nb * 64 + ks * 8 + lc];
                Breg[nt][ks][1] = Wg[nb * 64 + ks * 8 + lc + 4];
            }
        }
    }
    __syncthreads();

    // ---- per-warp epilogue constants ----
    float cbv[4][2], w2v[4][2];
    #pragma unroll
    for (int nt = 0; nt < 4; nt++) {
        int n0 = (warp * 4 + nt) * 8 + lc * 2;
        cbv[nt][0] = sm.cb[n0];     cbv[nt][1] = sm.cb[n0 + 1];
        w2v[nt][0] = sm.w2[n0];     w2v[nt][1] = sm.w2[n0 + 1];
    }

    // ---- GEMM: every warp sweeps all 13 slabs on its 4 n-tiles ----
    #pragma unroll 1
    for (int slab = 0; slab < 13; slab++) {
        int r0 = slab * 16 + lr;
        float c[4][4];
        #pragma unroll
        for (int nt = 0; nt < 4; nt++)
            c[nt][0] = c[nt][1] = c[nt][2] = c[nt][3] = 0.f;
        #pragma unroll
        for (int ks = 0; ks < 8; ks++) {
            uint32_t a0 = Au[r0 * 68 + ks * 8 + lc];
            uint32_t a1 = Au[(r0 + 8) * 68 + ks * 8 + lc];
            uint32_t a2 = Au[r0 * 68 + ks * 8 + lc + 4];
            uint32_t a3 = Au[(r0 + 8) * 68 + ks * 8 + lc + 4];
            #pragma unroll
            for (int nt = 0; nt < 4; nt++)
                mma16816(c[nt][0], c[nt][1], c[nt][2], c[nt][3],
                         a0, a1, a2, a3, Breg[nt][ks][0], Breg[nt][ks][1]);
        }
        float lp0 = 0.f, lp1 = 0.f;
        #pragma unroll
        for (int nt = 0; nt < 4; nt++) {
            lp0 += fmaxf(c[nt][0] + cbv[nt][0], 0.f) * w2v[nt][0]
                 + fmaxf(c[nt][1] + cbv[nt][1], 0.f) * w2v[nt][1];
            lp1 += fmaxf(c[nt][2] + cbv[nt][0], 0.f) * w2v[nt][0]
                 + fmaxf(c[nt][3] + cbv[nt][1], 0.f) * w2v[nt][1];
        }
        lp0 += __shfl_xor_sync(0xffffffffu, lp0, 1);
        lp0 += __shfl_xor_sync(0xffffffffu, lp0, 2);
        lp1 += __shfl_xor_sync(0xffffffffu, lp1, 1);
        lp1 += __shfl_xor_sync(0xffffffffu, lp1, 2);
        if (lc == 0) {
            atomicAdd(&sm.logits[r0], lp0);
            atomicAdd(&sm.logits[r0 + 8], lp1);
        }
    }
    __syncthreads();

    // ---- softmax over 200 logits ----
    {
        float v = (tid < SEQ) ? sm.logits[tid] : -1e30f;
        float m = v;
        #pragma unroll
        for (int o = 16; o > 0; o >>= 1) m = fmaxf(m, __shfl_xor_sync(0xffffffffu, m, o));
        if (lane == 0) sm.red[warp] = m;
        __syncthreads();
        if (tid == 0) {
            float mm = sm.red[0];
            #pragma unroll
            for (int w = 1; w < 8; w++) mm = fmaxf(mm, sm.red[w]);
            sm.red[8] = mm;
        }
        __syncthreads();
        float mm = sm.red[8];
        float ev = (tid < SEQ) ? __expf(v - mm) : 0.f;
        float s = ev;
        #pragma unroll
        for (int o = 16; o > 0; o >>= 1) s += __shfl_xor_sync(0xffffffffu, s, o);
        if (lane == 0) sm.red[16 + warp] = s;
        __syncthreads();
        if (tid == 0) {
            float ss = 0.f;
            #pragma unroll
            for (int w = 0; w < 8; w++) ss += sm.red[16 + w];
            sm.red[9] = 1.f / ss;
        }
        __syncthreads();
        if (tid < SEQ) sm.logits[tid] = ev * sm.red[9];
    }
    __syncthreads();

    // ---- weighted pooling straight from the bf16 A tile ----
    {
        int e2 = tid & 31, chunk = tid >> 5;       // warp = one 25-row chunk
        float acc0 = 0.f, acc1 = 0.f;
        int s0 = chunk * 25;
        #pragma unroll 5
        for (int s = s0; s < s0 + 25; s++) {
            float w = sm.logits[s];
            uint32_t u = Au[s * 68 + e2];
            __nv_bfloat162 h2 = *reinterpret_cast<__nv_bfloat162*>(&u);
            acc0 = fmaf(w, __bfloat162float(h2.x), acc0);
            acc1 = fmaf(w, __bfloat162float(h2.y), acc1);
        }
        sm.part[chunk][e2 * 2]     = acc0;
        sm.part[chunk][e2 * 2 + 1] = acc1;
    }
    __syncthreads();
    if (tid < 64) {
        float v = 0.f;
        #pragma unroll
        for (int c8 = 0; c8 < 8; c8++) v += sm.part[c8][tid];
        g_x[b * 128 + tid] = v;
    }
}

// ================= kernel 2: prediction head =================
struct Smem2 {
    float w1[128 * 256];
    float b1[256];
    float w2[256];
    float xs[8 * 4 * 128];
};

__global__ __launch_bounds__(256, 1) void din_mlp(
    const float* __restrict__ mw1, const float* __restrict__ mb1,
    const float* __restrict__ mw2, const float* __restrict__ mb2,
    float* __restrict__ out)
{
    extern __shared__ char smraw[];
    Smem2& sm = *reinterpret_cast<Smem2*>(smraw);
    const int tid = threadIdx.x;

    for (int i = tid; i < 128 * 256; i += 256) sm.w1[i] = mw1[i];
    sm.b1[tid] = mb1[tid];
    sm.w2[tid] = mw2[tid];
    __syncthreads();

    const int warp = tid >> 5, lane = tid & 31;
    const int row0 = blockIdx.x * 32 + warp * 4;

    float4* xs4 = reinterpret_cast<float4*>(sm.xs + warp * 512);
    const float4* gx4 = reinterpret_cast<const float4*>(g_x);
    #pragma unroll
    for (int r = 0; r < 4; r++) xs4[r * 32 + lane] = gx4[(long)(row0 + r) * 32 + lane];
    __syncwarp();

    float d[4][8];
    #pragma unroll
    for (int r = 0; r < 4; r++)
        #pragma unroll
        for (int u = 0; u < 8; u++) d[r][u] = sm.b1[u * 32 + lane];

    const float* xw = sm.xs + warp * 512;
    for (int k = 0; k < 128; k++) {
        float w[8];
        #pragma unroll
        for (int u = 0; u < 8; u++) w[u] = sm.w1[k * 256 + u * 32 + lane];
        #pragma unroll
        for (int r = 0; r < 4; r++) {
            float xk = xw[r * 128 + k];
            #pragma unroll
            for (int u = 0; u < 8; u++) d[r][u] = fmaf(xk, w[u], d[r][u]);
        }
    }

    float b2v = mb2[0];
    float acc[4];
    #pragma unroll
    for (int r = 0; r < 4; r++) {
        float a = 0.f;
        #pragma unroll
        for (int u = 0; u < 8; u++) a += fmaxf(d[r][u], 0.f) * sm.w2[u * 32 + lane];
        #pragma unroll
        for (int o = 16; o > 0; o >>= 1) a += __shfl_xor_sync(0xffffffffu, a, o);
        acc[r] = a;
    }
    if (lane < 4) {
        float z = acc[lane] + b2v;
        out[row0 + lane] = 1.f / (1.f + __expf(-z));
    }
}

// ================= launch =================
extern "C" void kernel_launch(void* const* d_in, const int* in_sizes, int n_in,
                              void* d_out, int out_size) {
    const int*   uh   = (const int*)d_in[0];
    const int*   ti   = (const int*)d_in[1];
    const float* uemb = (const float*)d_in[2];
    const float* iemb = (const float*)d_in[3];
    const float* aw1  = (const float*)d_in[4];
    const float* ab1  = (const float*)d_in[5];
    const float* aw2  = (const float*)d_in[6];
    // d_in[7] attn_b2: softmax-invariant, unused
    const float* mw1  = (const float*)d_in[8];
    const float* mb1  = (const float*)d_in[9];
    const float* mw2  = (const float*)d_in[10];
    const float* mb2  = (const float*)d_in[11];
    float* out = (float*)d_out;

    cudaFuncSetAttribute(prep_kernel, cudaFuncAttributeMaxDynamicSharedMemorySize, (int)sizeof(SmemP));
    cudaFuncSetAttribute(din_main,    cudaFuncAttributeMaxDynamicSharedMemorySize, (int)sizeof(Smem1));
    cudaFuncSetAttribute(din_mlp,     cudaFuncAttributeMaxDynamicSharedMemorySize, (int)sizeof(Smem2));

    prep_kernel<<<128, 256, sizeof(SmemP)>>>(aw1, ab1, ti, iemb);
    din_main<<<BATCH, 256, sizeof(Smem1)>>>(uh, uemb, aw2);
    din_mlp<<<128, 256, sizeof(Smem2)>>>(mw1, mb1, mw2, mb2, out);
}

// round 5
// speedup vs baseline: 2.1067x; 1.2168x over previous
#include <cuda_runtime.h>
#include <cuda_bf16.h>
#include <cstdint>

#define EMB 64
#define HID 256
#define SEQ 200
#define BATCH 4096

// -------- device scratch (no allocations allowed) --------
__device__ __align__(16) __nv_bfloat16 g_Wt[256 * 128];    // folded attn W, [n][k]
__device__ __align__(16) float        g_cb[BATCH * 256];   // per-batch folded bias
__device__ __align__(16) float        g_x[BATCH * 128];    // [interest | t] per batch row

// ================= prep: fold W, gather t, compute c_b (batch-parallel) =================
// grid 512 x 256: block p handles batches [p*8, p*8+8)
__global__ __launch_bounds__(256) void prep_kernel(
    const float* __restrict__ aw1, const float* __restrict__ ab1,
    const int* __restrict__ ti, const float* __restrict__ iemb)
{
    __shared__ float ts[8][64];
    __shared__ int   tis[8];
    const int tid = threadIdx.x;
    const int b0 = blockIdx.x * 8;

    // fold Wt (first 128 blocks cover 32768 elements)
    if (blockIdx.x < 128) {
        int idx = blockIdx.x * 256 + tid;
        int n = idx >> 7, k = idx & 127;
        float v = aw1[(128 + k) * HID + n];
        if (k < 64) v += aw1[k * HID + n];
        g_Wt[n * 128 + k] = __float2bfloat16(v);
    }

    if (tid < 8) tis[tid] = ti[b0 + tid];
    __syncthreads();
    #pragma unroll
    for (int i = tid; i < 512; i += 256) {
        int row = i >> 6, e = i & 63;
        float v = iemb[(long)tis[row] * EMB + e];
        ts[row][e] = v;
        g_x[(b0 + row) * 128 + 64 + e] = v;
    }
    __syncthreads();

    // c_b[b][n] = b1[n] + sum_e t[b][e] * (W1[64+e][n] - W1[128+e][n])
    const int n = tid;
    float acc[8];
    float bias = ab1[n];
    #pragma unroll
    for (int bb = 0; bb < 8; bb++) acc[bb] = bias;
    #pragma unroll 4
    for (int e = 0; e < 64; e++) {
        float m = aw1[(64 + e) * HID + n] - aw1[(128 + e) * HID + n];
        #pragma unroll
        for (int bb = 0; bb < 8; bb++) acc[bb] = fmaf(ts[bb][e], m, acc[bb]);
    }
    #pragma unroll
    for (int bb = 0; bb < 8; bb++) g_cb[(b0 + bb) * 256 + n] = acc[bb];
}

// ================= kernel 1: gather + attention GEMM + softmax + pool =================
struct Smem1 {
    __nv_bfloat16 A[208 * 136];   // [h | h*t] bf16, padded stride 136 (68 uint32)
    float t[64];
    float cb[256];
    float w2[256];
    float logits[208];
    float red[40];
    int   idx[200];
    float part[8][64];
};

__device__ __forceinline__ void mma16816(float& c0, float& c1, float& c2, float& c3,
                                         uint32_t a0, uint32_t a1, uint32_t a2, uint32_t a3,
                                         uint32_t b0, uint32_t b1) {
    asm volatile(
        "mma.sync.aligned.m16n8k16.row.col.f32.bf16.bf16.f32 "
        "{%0,%1,%2,%3}, {%4,%5,%6,%7}, {%8,%9}, {%0,%1,%2,%3};\n"
        : "+f"(c0), "+f"(c1), "+f"(c2), "+f"(c3)
        : "r"(a0), "r"(a1), "r"(a2), "r"(a3), "r"(b0), "r"(b1));
}

__global__ __launch_bounds__(256, 2) void din_main(
    const int* __restrict__ uh,
    const float* __restrict__ uemb,
    const float* __restrict__ aw2)
{
    extern __shared__ char smraw[];
    Smem1& sm = *reinterpret_cast<Smem1*>(smraw);
    const int tid = threadIdx.x;
    const int b = blockIdx.x;
    uint32_t* Au = reinterpret_cast<uint32_t*>(sm.A);
    const int warp = tid >> 5, lane = tid & 31;
    const int lr = lane >> 2, lc = lane & 3;

    // ---- stage indices, t, cb, w2; zero pads ----
    if (tid < 200) sm.idx[tid] = uh[b * SEQ + tid];
    if (tid >= 192) sm.t[tid - 192] = g_x[b * 128 + 64 + (tid - 192)];
    sm.cb[tid] = g_cb[b * 256 + tid];
    sm.w2[tid] = aw2[tid];
    if (tid < 208) sm.logits[tid] = 0.f;
    for (int i = tid; i < 8 * 68; i += 256) Au[200 * 68 + i] = 0u;  // pad rows 200..207
    __syncthreads();

    // ---- gather h: front-batch 13 independent LDG.128, then convert+store ----
    {
        const float4* ue4 = reinterpret_cast<const float4*>(uemb);
        float4 v[13];
        int row[13], q[13];
        #pragma unroll
        for (int it = 0; it < 13; it++) {
            int i = tid + it * 256;
            row[it] = i >> 4; q[it] = i & 15;
            if (i < 3200) v[it] = ue4[(long)sm.idx[row[it]] * 16 + q[it]];
        }
        #pragma unroll
        for (int it = 0; it < 13; it++) {
            int i = tid + it * 256;
            if (i < 3200) {
                float4 vv = v[it];
                int qq = q[it];
                float t0 = sm.t[qq * 4 + 0], t1 = sm.t[qq * 4 + 1];
                float t2 = sm.t[qq * 4 + 2], t3 = sm.t[qq * 4 + 3];
                __nv_bfloat162 p0 = __floats2bfloat162_rn(vv.x, vv.y);
                __nv_bfloat162 p1 = __floats2bfloat162_rn(vv.z, vv.w);
                __nv_bfloat162 q0 = __floats2bfloat162_rn(vv.x * t0, vv.y * t1);
                __nv_bfloat162 q1 = __floats2bfloat162_rn(vv.z * t2, vv.w * t3);
                int base = row[it] * 68 + qq * 2;
                uint2 P; P.x = *reinterpret_cast<uint32_t*>(&p0); P.y = *reinterpret_cast<uint32_t*>(&p1);
                uint2 Q; Q.x = *reinterpret_cast<uint32_t*>(&q0); Q.y = *reinterpret_cast<uint32_t*>(&q1);
                *reinterpret_cast<uint2*>(Au + base) = P;
                *reinterpret_cast<uint2*>(Au + base + 32) = Q;
            }
        }
    }

    // ---- B fragments: this warp's 4 n-tiles, straight from L2 into regs ----
    uint32_t Breg[4][8][2];
    {
        const uint32_t* Wg = reinterpret_cast<const uint32_t*>(g_Wt);
        #pragma unroll
        for (int nt = 0; nt < 4; nt++) {
            int nb = (warp * 4 + nt) * 8 + lr;
            #pragma unroll
            for (int ks = 0; ks < 8; ks++) {
                Breg[nt][ks][0] = Wg[nb * 64 + ks * 8 + lc];
                Breg[nt][ks][1] = Wg[nb * 64 + ks * 8 + lc + 4];
            }
        }
    }
    __syncthreads();

    // ---- per-warp epilogue constants ----
    float cbv[4][2], w2v[4][2];
    #pragma unroll
    for (int nt = 0; nt < 4; nt++) {
        int n0 = (warp * 4 + nt) * 8 + lc * 2;
        cbv[nt][0] = sm.cb[n0];     cbv[nt][1] = sm.cb[n0 + 1];
        w2v[nt][0] = sm.w2[n0];     w2v[nt][1] = sm.w2[n0 + 1];
    }

    // per-lane ldmatrix base: row r0 + (lane&15), k-half select via (lane&16)
    const uint32_t abase = (uint32_t)__cvta_generic_to_shared(Au);
    const uint32_t rowsel = (lane & 15);
    const uint32_t khalf  = (lane & 16) ? 16u : 0u;

    // ---- GEMM: every warp sweeps all 13 slabs on its 4 n-tiles ----
    #pragma unroll 1
    for (int slab = 0; slab < 13; slab++) {
        int r0 = slab * 16 + lr;
        uint32_t lmbase = abase + (slab * 16 + rowsel) * 272 + khalf;
        uint32_t a[8][4];
        #pragma unroll
        for (int ks = 0; ks < 8; ks++) {
            asm volatile(
                "ldmatrix.sync.aligned.m8n8.x4.shared.b16 {%0,%1,%2,%3}, [%4];\n"
                : "=r"(a[ks][0]), "=r"(a[ks][1]), "=r"(a[ks][2]), "=r"(a[ks][3])
                : "r"(lmbase + ks * 32));
        }
        float c[4][4];
        #pragma unroll
        for (int nt = 0; nt < 4; nt++)
            c[nt][0] = c[nt][1] = c[nt][2] = c[nt][3] = 0.f;
        #pragma unroll
        for (int ks = 0; ks < 8; ks++) {
            #pragma unroll
            for (int nt = 0; nt < 4; nt++)
                mma16816(c[nt][0], c[nt][1], c[nt][2], c[nt][3],
                         a[ks][0], a[ks][1], a[ks][2], a[ks][3],
                         Breg[nt][ks][0], Breg[nt][ks][1]);
        }
        float lp0 = 0.f, lp1 = 0.f;
        #pragma unroll
        for (int nt = 0; nt < 4; nt++) {
            lp0 += fmaxf(c[nt][0] + cbv[nt][0], 0.f) * w2v[nt][0]
                 + fmaxf(c[nt][1] + cbv[nt][1], 0.f) * w2v[nt][1];
            lp1 += fmaxf(c[nt][2] + cbv[nt][0], 0.f) * w2v[nt][0]
                 + fmaxf(c[nt][3] + cbv[nt][1], 0.f) * w2v[nt][1];
        }
        lp0 += __shfl_xor_sync(0xffffffffu, lp0, 1);
        lp0 += __shfl_xor_sync(0xffffffffu, lp0, 2);
        lp1 += __shfl_xor_sync(0xffffffffu, lp1, 1);
        lp1 += __shfl_xor_sync(0xffffffffu, lp1, 2);
        if (lc == 0) {
            atomicAdd(&sm.logits[r0], lp0);
            atomicAdd(&sm.logits[r0 + 8], lp1);
        }
    }
    __syncthreads();

    // ---- softmax over 200 logits ----
    {
        float v = (tid < SEQ) ? sm.logits[tid] : -1e30f;
        float m = v;
        #pragma unroll
        for (int o = 16; o > 0; o >>= 1) m = fmaxf(m, __shfl_xor_sync(0xffffffffu, m, o));
        if (lane == 0) sm.red[warp] = m;
        __syncthreads();
        if (tid == 0) {
            float mm = sm.red[0];
            #pragma unroll
            for (int w = 1; w < 8; w++) mm = fmaxf(mm, sm.red[w]);
            sm.red[8] = mm;
        }
        __syncthreads();
        float mm = sm.red[8];
        float ev = (tid < SEQ) ? __expf(v - mm) : 0.f;
        float s = ev;
        #pragma unroll
        for (int o = 16; o > 0; o >>= 1) s += __shfl_xor_sync(0xffffffffu, s, o);
        if (lane == 0) sm.red[16 + warp] = s;
        __syncthreads();
        if (tid == 0) {
            float ss = 0.f;
            #pragma unroll
            for (int w = 0; w < 8; w++) ss += sm.red[16 + w];
            sm.red[9] = 1.f / ss;
        }
        __syncthreads();
        if (tid < SEQ) sm.logits[tid] = ev * sm.red[9];
    }
    __syncthreads();

    // ---- weighted pooling straight from the bf16 A tile ----
    {
        int e2 = tid & 31, chunk = tid >> 5;       // warp = one 25-row chunk
        float acc0 = 0.f, acc1 = 0.f;
        int s0 = chunk * 25;
        #pragma unroll 5
        for (int s = s0; s < s0 + 25; s++) {
            float w = sm.logits[s];
            uint32_t u = Au[s * 68 + e2];
            __nv_bfloat162 h2 = *reinterpret_cast<__nv_bfloat162*>(&u);
            acc0 = fmaf(w, __bfloat162float(h2.x), acc0);
            acc1 = fmaf(w, __bfloat162float(h2.y), acc1);
        }
        sm.part[chunk][e2 * 2]     = acc0;
        sm.part[chunk][e2 * 2 + 1] = acc1;
    }
    __syncthreads();
    if (tid < 64) {
        float v = 0.f;
        #pragma unroll
        for (int c8 = 0; c8 < 8; c8++) v += sm.part[c8][tid];
        g_x[b * 128 + tid] = v;
    }
}

// ================= kernel 2: prediction head =================
struct Smem2 {
    float w1[128 * 256];
    float b1[256];
    float w2[256];
    float xs[8 * 4 * 128];
};

__global__ __launch_bounds__(256, 1) void din_mlp(
    const float* __restrict__ mw1, const float* __restrict__ mb1,
    const float* __restrict__ mw2, const float* __restrict__ mb2,
    float* __restrict__ out)
{
    extern __shared__ char smraw[];
    Smem2& sm = *reinterpret_cast<Smem2*>(smraw);
    const int tid = threadIdx.x;

    for (int i = tid; i < 128 * 256; i += 256) sm.w1[i] = mw1[i];
    sm.b1[tid] = mb1[tid];
    sm.w2[tid] = mw2[tid];
    __syncthreads();

    const int warp = tid >> 5, lane = tid & 31;
    const int row0 = blockIdx.x * 32 + warp * 4;

    float4* xs4 = reinterpret_cast<float4*>(sm.xs + warp * 512);
    const float4* gx4 = reinterpret_cast<const float4*>(g_x);
    #pragma unroll
    for (int r = 0; r < 4; r++) xs4[r * 32 + lane] = gx4[(long)(row0 + r) * 32 + lane];
    __syncwarp();

    float d[4][8];
    #pragma unroll
    for (int r = 0; r < 4; r++)
        #pragma unroll
        for (int u = 0; u < 8; u++) d[r][u] = sm.b1[u * 32 + lane];

    const float* xw = sm.xs + warp * 512;
    for (int k = 0; k < 128; k++) {
        float w[8];
        #pragma unroll
        for (int u = 0; u < 8; u++) w[u] = sm.w1[k * 256 + u * 32 + lane];
        #pragma unroll
        for (int r = 0; r < 4; r++) {
            float xk = xw[r * 128 + k];
            #pragma unroll
            for (int u = 0; u < 8; u++) d[r][u] = fmaf(xk, w[u], d[r][u]);
        }
    }

    float b2v = mb2[0];
    float acc[4];
    #pragma unroll
    for (int r = 0; r < 4; r++) {
        float a = 0.f;
        #pragma unroll
        for (int u = 0; u < 8; u++) a += fmaxf(d[r][u], 0.f) * sm.w2[u * 32 + lane];
        #pragma unroll
        for (int o = 16; o > 0; o >>= 1) a += __shfl_xor_sync(0xffffffffu, a, o);
        acc[r] = a;
    }
    if (lane < 4) {
        float z = acc[lane] + b2v;
        out[row0 + lane] = 1.f / (1.f + __expf(-z));
    }
}

// ================= launch =================
extern "C" void kernel_launch(void* const* d_in, const int* in_sizes, int n_in,
                              void* d_out, int out_size) {
    const int*   uh   = (const int*)d_in[0];
    const int*   ti   = (const int*)d_in[1];
    const float* uemb = (const float*)d_in[2];
    const float* iemb = (const float*)d_in[3];
    const float* aw1  = (const float*)d_in[4];
    const float* ab1  = (const float*)d_in[5];
    const float* aw2  = (const float*)d_in[6];
    // d_in[7] attn_b2: softmax-invariant, unused
    const float* mw1  = (const float*)d_in[8];
    const float* mb1  = (const float*)d_in[9];
    const float* mw2  = (const float*)d_in[10];
    const float* mb2  = (const float*)d_in[11];
    float* out = (float*)d_out;

    cudaFuncSetAttribute(din_main, cudaFuncAttributeMaxDynamicSharedMemorySize, (int)sizeof(Smem1));
    cudaFuncSetAttribute(din_mlp,  cudaFuncAttributeMaxDynamicSharedMemorySize, (int)sizeof(Smem2));

    prep_kernel<<<512, 256>>>(aw1, ab1, ti, iemb);
    din_main<<<BATCH, 256, sizeof(Smem1)>>>(uh, uemb, aw2);
    din_mlp<<<128, 256, sizeof(Smem2)>>>(mw1, mb1, mw2, mb2, out);
}